// round 12
// baseline (speedup 1.0000x reference)
#include <cuda_runtime.h>
#include <cuda_fp16.h>
#include <cstdint>

// ---------------------------------------------------------------------------
// B=16, C=1024, N=1024, T=77(pad 80), heads=8, hd=128.  All GEMMs fp16
// mma.sync.m16n8k16 (fp32 accum) + ldmatrix.
//   big GEMMs (Q, Y): 256x128x32 tiles, 8 warps, cp.async.bulk + mbarrier
//     (288 bulk ops/tile vs 1536 LDGSTS -> LSU issue floor no longer binds)
//   small GEMMs (KV, S+softmax, O): 128x128x32 tiles, cp.async (16B)
// Softmax fused into S-GEMM epilogue. Scratch fp16; cols 77..79 stored zero.
// KV head split: K_h rows [256h,256h+128), V_h rows [256h+128,256h+256).
// ---------------------------------------------------------------------------

#define NB 16
#define CC 1024
#define NN 1024
#define TT 77
#define TP 80
#define NH 8
#define HD 128

__device__ __half h_Vx[(size_t)NB * CC * NN];
__device__ __half h_Tx[(size_t)NB * CC * TP];
__device__ __half h_Wq[(size_t)CC * CC];
__device__ __half h_Wkv[(size_t)2 * CC * CC];
__device__ __half h_Wp[(size_t)CC * CC];
__device__ __half h_Q [(size_t)NB * CC * NN];
__device__ __half h_KV[(size_t)NB * 2 * CC * TP];
__device__ __half h_P [(size_t)NB * NH * NN * TP];
__device__ __half h_O [(size_t)NB * CC * NN];

__device__ __forceinline__ uint32_t smem_u32(const void* p) {
    uint32_t a;
    asm("{ .reg .u64 t; cvta.to.shared.u64 t, %1; cvt.u32.u64 %0, t; }" : "=r"(a) : "l"(p));
    return a;
}
#define CP16(d, s, sz) asm volatile("cp.async.cg.shared.global [%0], [%1], 16, %2;" :: "r"(d), "l"(s), "r"(sz) : "memory")
#define CP_COMMIT()    asm volatile("cp.async.commit_group;" ::: "memory")
#define CP_WAIT1()     asm volatile("cp.async.wait_group 1;" ::: "memory")

// --- bulk async copy + mbarrier (sm_90 base PTX; no 'a' features) ---
#define BULK(dst, src, bytes, mbar) \
    asm volatile("cp.async.bulk.shared::cluster.global.mbarrier::complete_tx::bytes [%0], [%1], %2, [%3];" \
        :: "r"(dst), "l"(src), "r"(bytes), "r"(mbar) : "memory")
#define MBAR_INIT(a, c)  asm volatile("mbarrier.init.shared.b64 [%0], %1;" :: "r"(a), "r"(c) : "memory")
#define EXPECT_TX(a, b)  asm volatile("mbarrier.arrive.expect_tx.shared.b64 _, [%0], %1;" :: "r"(a), "r"(b) : "memory")
#define FENCE_ASYNC()    asm volatile("fence.proxy.async.shared::cta;" ::: "memory")
#define MBAR_WAIT(a, ph) do {                                                    \
    uint32_t _m = (a), _p = (ph), _d;                                            \
    asm volatile("{\n\t.reg .pred p;\n\t"                                        \
        "mbarrier.try_wait.parity.acquire.cta.shared::cta.b64 p, [%1], %2;\n\t"  \
        "selp.b32 %0, 1, 0, p;\n\t}" : "=r"(_d) : "r"(_m), "r"(_p) : "memory");  \
    if (!_d) {                                                                   \
        asm volatile("{\n\t.reg .pred P1;\n\tWL_%=:\n\t"                         \
        "mbarrier.try_wait.parity.acquire.cta.shared::cta.b64 P1, [%0], %1, 0x989680;\n\t" \
        "@P1 bra.uni WD_%=;\n\tbra.uni WL_%=;\n\tWD_%=:\n\t}"                    \
        :: "r"(_m), "r"(_p) : "memory");                                         \
    } } while (0)

#define LDSM_X4(r0, r1, r2, r3, a) \
    asm volatile("ldmatrix.sync.aligned.m8n8.x4.shared.b16 {%0,%1,%2,%3}, [%4];" \
        : "=r"(r0), "=r"(r1), "=r"(r2), "=r"(r3) : "r"(a))
#define LDSM_X4T(r0, r1, r2, r3, a) \
    asm volatile("ldmatrix.sync.aligned.m8n8.x4.trans.shared.b16 {%0,%1,%2,%3}, [%4];" \
        : "=r"(r0), "=r"(r1), "=r"(r2), "=r"(r3) : "r"(a))

__device__ __forceinline__ void mma_f16(float* c, const uint32_t* a, const uint32_t* b) {
    asm volatile(
        "mma.sync.aligned.m16n8k16.row.col.f32.f16.f16.f32 "
        "{%0,%1,%2,%3}, {%4,%5,%6,%7}, {%8,%9}, {%0,%1,%2,%3};\n"
        : "+f"(c[0]), "+f"(c[1]), "+f"(c[2]), "+f"(c[3])
        : "r"(a[0]), "r"(a[1]), "r"(a[2]), "r"(a[3]), "r"(b[0]), "r"(b[1]));
}

// ===========================================================================
// BIG GEMM: C[z][m,n] = A[m,:]@B[z][:,n] + bias[m].  M=N=K=1024, z=16.
// Tile 256x128x32, 256 thr, 8 warps (4m x 2n), warp tile 64x64.
// Loads: cp.async.bulk, one op per smem row (A: 256 x 64B, B: 32 x 256B),
// completion via per-stage mbarrier expect_tx/complete_tx (24576 B/stage).
// OM: 0 = fp32 out, 1 = fp16 out.
// ===========================================================================
#define BIG_A_B 20480                      // 256 rows * 40h * 2B
#define BIG_B_B 8704                       // 32 rows * 136h * 2B
#define BIG_STAGE (BIG_A_B + BIG_B_B)      // 29184
#define BIG_TILES_B (BIG_STAGE * 3)        // 87552
#define BIG_SMEM (BIG_TILES_B + 64)        // + mbarriers

template <int OM>
__global__ __launch_bounds__(256, 1)
void hgemm_big(const __half* __restrict__ A, const __half* __restrict__ B,
               void* __restrict__ Cv, const float* __restrict__ bias,
               long long sBb, long long sCb)
{
    extern __shared__ char smem[];
    const uint32_t sb = smem_u32(smem);
    const uint32_t mbars = sb + BIG_TILES_B;

    const int tid  = threadIdx.x;
    const int lane = tid & 31;
    const int warp = tid >> 5;          // 0..7
    const int wm = (warp & 3) * 64;     // 4 warps along M
    const int wn = (warp >> 2) * 64;    // 2 warps along N
    const int gid = lane >> 2;
    const int tig = lane & 3;
    const int tl  = lane >> 3;
    const int rr  = lane & 7;

    const int m0 = blockIdx.y * 256;
    const int n0 = blockIdx.x * 128;
    const __half* Bb = B + (size_t)blockIdx.z * sBb;

    if (tid == 0) {
        MBAR_INIT(mbars + 0, 1);
        MBAR_INIT(mbars + 8, 1);
        MBAR_INIT(mbars + 16, 1);
    }
    FENCE_ASYNC();
    __syncthreads();

    // one bulk row per thread for A, 32 threads for B; thread 0 sets tx.
    auto load_tile = [&](int kt, int s) {
        const int k0 = kt << 5;
        const uint32_t aB = sb + (uint32_t)s * BIG_STAGE;
        const uint32_t bB = aB + BIG_A_B;
        const uint32_t mb = mbars + (uint32_t)s * 8;
        if (tid == 0) EXPECT_TX(mb, 24576u);
        BULK(aB + (uint32_t)tid * 80u,
             A + (size_t)(m0 + tid) * CC + k0, 64u, mb);
        if (tid < 32)
            BULK(bB + (uint32_t)tid * 272u,
                 Bb + (size_t)(k0 + tid) * NN + n0, 256u, mb);
    };

    float acc[4][8][4];
    #pragma unroll
    for (int mi = 0; mi < 4; mi++)
        #pragma unroll
        for (int ni = 0; ni < 8; ni++)
            #pragma unroll
            for (int j = 0; j < 4; j++) acc[mi][ni][j] = 0.f;

    load_tile(0, 0);
    load_tile(1, 1);

    unsigned phbits = 0;                 // phase parity per stage
    const int nkt = CC >> 5;
    for (int kt = 0; kt < nkt; kt++) {
        const int s = kt % 3;
        MBAR_WAIT(mbars + (uint32_t)s * 8, (phbits >> s) & 1u);
        phbits ^= 1u << s;
        __syncthreads();                 // all warps done reading stage (kt+2)%3
        if (kt + 2 < nkt) load_tile(kt + 2, (kt + 2) % 3);

        const uint32_t aB = sb + (uint32_t)(s * BIG_STAGE);
        const uint32_t bB = aB + BIG_A_B;

        #pragma unroll
        for (int kk = 0; kk < 32; kk += 16) {
            uint32_t afr[4][4], bfr[8][2];
            #pragma unroll
            for (int mi = 0; mi < 4; mi++) {
                uint32_t addr = aB + (uint32_t)((wm + mi * 16 + (tl & 1) * 8 + rr) * 40
                                                + kk + (tl >> 1) * 8) * 2;
                LDSM_X4(afr[mi][0], afr[mi][1], afr[mi][2], afr[mi][3], addr);
            }
            #pragma unroll
            for (int np = 0; np < 4; np++) {
                uint32_t addr = bB + (uint32_t)((kk + (tl & 1) * 8 + rr) * 136
                                                + wn + np * 16 + (tl >> 1) * 8) * 2;
                LDSM_X4T(bfr[2*np][0], bfr[2*np][1], bfr[2*np+1][0], bfr[2*np+1][1], addr);
            }
            #pragma unroll
            for (int mi = 0; mi < 4; mi++)
                #pragma unroll
                for (int ni = 0; ni < 8; ni++)
                    mma_f16(acc[mi][ni], afr[mi], bfr[ni]);
        }
    }

    #pragma unroll
    for (int mi = 0; mi < 4; mi++) {
        int r0 = m0 + wm + mi * 16 + gid;
        float bv0 = bias[r0];
        float bv1 = bias[r0 + 8];
        #pragma unroll
        for (int ni = 0; ni < 8; ni++) {
            int c0 = n0 + wn + ni * 8 + 2 * tig;
            if (OM == 0) {
                float* Cb = (float*)Cv + (size_t)blockIdx.z * sCb;
                Cb[(size_t)r0 * NN + c0]           = acc[mi][ni][0] + bv0;
                Cb[(size_t)r0 * NN + c0 + 1]       = acc[mi][ni][1] + bv0;
                Cb[(size_t)(r0 + 8) * NN + c0]     = acc[mi][ni][2] + bv1;
                Cb[(size_t)(r0 + 8) * NN + c0 + 1] = acc[mi][ni][3] + bv1;
            } else {
                __half* Cb = (__half*)Cv + (size_t)blockIdx.z * sCb;
                Cb[(size_t)r0 * NN + c0]           = __float2half(acc[mi][ni][0] + bv0);
                Cb[(size_t)r0 * NN + c0 + 1]       = __float2half(acc[mi][ni][1] + bv0);
                Cb[(size_t)(r0 + 8) * NN + c0]     = __float2half(acc[mi][ni][2] + bv1);
                Cb[(size_t)(r0 + 8) * NN + c0 + 1] = __float2half(acc[mi][ni][3] + bv1);
            }
        }
    }
}

// ===========================================================================
// Small generic GEMM (KV, S+softmax, O) — unchanged from round 9.
// ===========================================================================
#define STAGE_B 20480

template <bool AT, bool BT, int OM>
__global__ __launch_bounds__(256, 2)
void hgemm(const __half* __restrict__ A, const __half* __restrict__ B,
           void* __restrict__ Cv, const float* __restrict__ bias,
           int M, int N, int K,
           long long sA, long long sB, long long ldc,
           long long sAb, long long sAh, long long sBb, long long sBh,
           long long sCb, long long sCh, int nh, float alpha,
           int Ka, int Bbound, int nvalid)
{
    extern __shared__ char smem[];
    const uint32_t sb = smem_u32(smem);

    const int tid  = threadIdx.x;
    const int lane = tid & 31;
    const int warp = tid >> 5;
    const int wm = (warp & 3) * 32;
    const int wn = (warp >> 2) * 64;
    const int gid = lane >> 2;
    const int tig = lane & 3;
    const int tl  = lane >> 3;
    const int rr  = lane & 7;

    const int z = blockIdx.z;
    const int b = z / nh;
    const int h = z - b * nh;
    const __half* Ab = A + (size_t)b * sAb + (size_t)h * sAh;
    const __half* Bb = B + (size_t)b * sBb + (size_t)h * sBh;

    const int m0 = blockIdx.y * 128;
    const int n0 = blockIdx.x * 128;
    const int nkt = (K + 31) >> 5;

    auto load_tile = [&](int kt, int s) {
        const int k0 = kt << 5;
        const uint32_t aB = sb + (uint32_t)s * STAGE_B;
        const uint32_t bB = aB + 10240;
        #pragma unroll
        for (int i = 0; i < 2; i++) {
            int sg = tid + i * 256;
            if (!AT) {
                int m = sg >> 2, sk = sg & 3;
                CP16(aB + (uint32_t)(m * 40 + sk * 8) * 2,
                     Ab + (size_t)(m0 + m) * sA + k0 + sk * 8,
                     (k0 + sk * 8 < Ka) ? 16 : 0);
            } else {
                int k = sg >> 4, sm = sg & 15;
                CP16(aB + (uint32_t)(k * 136 + sm * 8) * 2,
                     Ab + (size_t)(k0 + k) * sA + m0 + sm * 8, 16);
            }
        }
        #pragma unroll
        for (int i = 0; i < 2; i++) {
            int sg = tid + i * 256;
            if (BT) {
                int k = sg >> 4, sn = sg & 15;
                CP16(bB + (uint32_t)(k * 136 + sn * 8) * 2,
                     Bb + (size_t)(k0 + k) * sB + n0 + sn * 8,
                     (n0 + sn * 8 < Bbound) ? 16 : 0);
            } else {
                int n = sg >> 2, sk = sg & 3;
                CP16(bB + (uint32_t)(n * 40 + sk * 8) * 2,
                     Bb + (size_t)(n0 + n) * sB + k0 + sk * 8,
                     (k0 + sk * 8 < Bbound) ? 16 : 0);
            }
        }
        CP_COMMIT();
    };

    float acc[2][8][4];
    #pragma unroll
    for (int mi = 0; mi < 2; mi++)
        #pragma unroll
        for (int ni = 0; ni < 8; ni++)
            #pragma unroll
            for (int j = 0; j < 4; j++) acc[mi][ni][j] = 0.f;

    load_tile(0, 0);
    if (nkt > 1) load_tile(1, 1); else CP_COMMIT();

    for (int kt = 0; kt < nkt; kt++) {
        CP_WAIT1();
        __syncthreads();
        if (kt + 2 < nkt) load_tile(kt + 2, (kt + 2) % 3);
        else CP_COMMIT();

        const uint32_t aB = sb + (uint32_t)((kt % 3) * STAGE_B);
        const uint32_t bB = aB + 10240;

        #pragma unroll
        for (int kk = 0; kk < 32; kk += 16) {
            uint32_t afr[2][4], bfr[8][2];
            #pragma unroll
            for (int mi = 0; mi < 2; mi++) {
                uint32_t addr;
                if (!AT)
                    addr = aB + (uint32_t)((wm + mi * 16 + (tl & 1) * 8 + rr) * 40
                                           + kk + (tl >> 1) * 8) * 2;
                else
                    addr = aB + (uint32_t)((kk + (tl >> 1) * 8 + rr) * 136
                                           + wm + mi * 16 + (tl & 1) * 8) * 2;
                if (!AT) LDSM_X4 (afr[mi][0], afr[mi][1], afr[mi][2], afr[mi][3], addr);
                else     LDSM_X4T(afr[mi][0], afr[mi][1], afr[mi][2], afr[mi][3], addr);
            }
            #pragma unroll
            for (int np = 0; np < 4; np++) {
                int nb = wn + np * 16;
                uint32_t addr;
                if (BT)
                    addr = bB + (uint32_t)((kk + (tl & 1) * 8 + rr) * 136
                                           + nb + (tl >> 1) * 8) * 2;
                else
                    addr = bB + (uint32_t)((nb + (tl >> 1) * 8 + rr) * 40
                                           + kk + (tl & 1) * 8) * 2;
                if (BT) LDSM_X4T(bfr[2*np][0], bfr[2*np][1], bfr[2*np+1][0], bfr[2*np+1][1], addr);
                else    LDSM_X4 (bfr[2*np][0], bfr[2*np][1], bfr[2*np+1][0], bfr[2*np+1][1], addr);
            }
            #pragma unroll
            for (int mi = 0; mi < 2; mi++)
                #pragma unroll
                for (int ni = 0; ni < 8; ni++)
                    mma_f16(acc[mi][ni], afr[mi], bfr[ni]);
        }
    }

    if (OM == 1) {
        __half* Cb = (__half*)Cv + (size_t)b * sCb + (size_t)h * sCh;
        #pragma unroll
        for (int mi = 0; mi < 2; mi++) {
            int r0 = m0 + wm + mi * 16 + gid;
            float bv0 = bias ? bias[r0]     : 0.f;
            float bv1 = bias ? bias[r0 + 8] : 0.f;
            #pragma unroll
            for (int ni = 0; ni < 8; ni++) {
                int c0 = n0 + wn + ni * 8 + 2 * tig;
                if (c0 < N) {
                    #pragma unroll
                    for (int j = 0; j < 2; j++) {
                        int c = c0 + j;
                        bool v = (c < nvalid);
                        Cb[(size_t)r0 * ldc + c] =
                            __float2half(v ? alpha * acc[mi][ni][j] + bv0 : 0.f);
                        Cb[(size_t)(r0 + 8) * ldc + c] =
                            __float2half(v ? alpha * acc[mi][ni][2 + j] + bv1 : 0.f);
                    }
                }
            }
        }
    } else {
        // OM==2: softmax over cols [0,77), fp16 out, row pitch 80.
        __half* Cb = (__half*)Cv + (size_t)b * sCb + (size_t)h * sCh;
        float* st = (float*)smem;                        // [128][84]
        __syncthreads();
        #pragma unroll
        for (int mi = 0; mi < 2; mi++) {
            int rl = wm + mi * 16 + gid;
            #pragma unroll
            for (int ni = 0; ni < 8; ni++) {
                int c0 = wn + ni * 8 + 2 * tig;
                if (c0 < TP) {
                    st[rl * 84 + c0]            = alpha * acc[mi][ni][0];
                    st[rl * 84 + c0 + 1]        = alpha * acc[mi][ni][1];
                    st[(rl + 8) * 84 + c0]      = alpha * acc[mi][ni][2];
                    st[(rl + 8) * 84 + c0 + 1]  = alpha * acc[mi][ni][3];
                }
            }
        }
        __syncthreads();
        for (int i = 0; i < 16; i++) {
            int rl = warp * 16 + i;
            float* row = st + rl * 84;
            float x0 = row[lane];
            float x1 = row[lane + 32];
            float x2 = (lane + 64 < TT) ? row[lane + 64] : -1e30f;
            float m = fmaxf(x0, fmaxf(x1, x2));
            #pragma unroll
            for (int off = 16; off > 0; off >>= 1)
                m = fmaxf(m, __shfl_xor_sync(0xFFFFFFFFu, m, off));
            float e0 = __expf(x0 - m);
            float e1 = __expf(x1 - m);
            float e2 = (lane + 64 < TT) ? __expf(x2 - m) : 0.f;
            float s = e0 + e1 + e2;
            #pragma unroll
            for (int off = 16; off > 0; off >>= 1)
                s += __shfl_xor_sync(0xFFFFFFFFu, s, off);
            float inv = 1.f / s;
            __half* dst = Cb + (size_t)(m0 + rl) * TP;
            dst[lane]      = __float2half(e0 * inv);
            dst[lane + 32] = __float2half(e1 * inv);
            if (lane + 64 < TP)
                dst[lane + 64] = __float2half((lane + 64 < TT) ? e2 * inv : 0.f);
        }
    }
}

// ---------------------------------------------------------------- converters
#define N4_VX  (NB * CC * NN / 4)
#define N4_WQ  (CC * CC / 4)
#define N4_WKV (2 * CC * CC / 4)

__global__ void f2h_all(const float* __restrict__ Vx, const float* __restrict__ Wq,
                        const float* __restrict__ Wkv, const float* __restrict__ Wp,
                        __half* __restrict__ dVx, __half* __restrict__ dWq,
                        __half* __restrict__ dWkv, __half* __restrict__ dWp)
{
    int i = blockIdx.x * 256 + threadIdx.x;
    const float* s; __half* d; int j;
    if (i < N4_VX)                       { s = Vx;  d = dVx;  j = i; }
    else if (i < N4_VX + N4_WQ)          { s = Wq;  d = dWq;  j = i - N4_VX; }
    else if (i < N4_VX + N4_WQ + N4_WKV) { s = Wkv; d = dWkv; j = i - N4_VX - N4_WQ; }
    else                                 { s = Wp;  d = dWp;  j = i - N4_VX - N4_WQ - N4_WKV; }
    float4 v = reinterpret_cast<const float4*>(s)[j];
    __half2* d2 = reinterpret_cast<__half2*>(d);
    d2[2 * j]     = __floats2half2_rn(v.x, v.y);
    d2[2 * j + 1] = __floats2half2_rn(v.z, v.w);
}
__global__ void f2h_pad77(const float* __restrict__ s, __half* __restrict__ d, int rows)
{
    int r = blockIdx.x, c = threadIdx.x;
    if (c < TP)
        d[(size_t)r * TP + c] = __float2half((c < TT) ? s[(size_t)r * TT + c] : 0.f);
}

// ---------------------------------------------------------------- launch
extern "C" void kernel_launch(void* const* d_in, const int* in_sizes, int n_in,
                              void* d_out, int out_size)
{
    const float* Vx  = (const float*)d_in[0];
    const float* Tx  = (const float*)d_in[1];
    const float* Wq  = (const float*)d_in[2];
    const float* bq  = (const float*)d_in[3];
    const float* Wkv = (const float*)d_in[4];
    const float* bkv = (const float*)d_in[5];
    const float* Wp  = (const float*)d_in[6];
    const float* bp  = (const float*)d_in[7];
    float* Y = (float*)d_out;

    __half *hVx, *hTx, *hWq, *hWkv, *hWp, *hQ, *hKV, *hP, *hO;
    cudaGetSymbolAddress((void**)&hVx, h_Vx);
    cudaGetSymbolAddress((void**)&hTx, h_Tx);
    cudaGetSymbolAddress((void**)&hWq, h_Wq);
    cudaGetSymbolAddress((void**)&hWkv, h_Wkv);
    cudaGetSymbolAddress((void**)&hWp, h_Wp);
    cudaGetSymbolAddress((void**)&hQ,  h_Q);
    cudaGetSymbolAddress((void**)&hKV, h_KV);
    cudaGetSymbolAddress((void**)&hP,  h_P);
    cudaGetSymbolAddress((void**)&hO,  h_O);

    constexpr int SMEM_SMALL = STAGE_B * 3;   // 61440
    cudaFuncSetAttribute(hgemm<false, true, 1>, cudaFuncAttributeMaxDynamicSharedMemorySize, SMEM_SMALL);
    cudaFuncSetAttribute(hgemm<true,  true, 2>, cudaFuncAttributeMaxDynamicSharedMemorySize, SMEM_SMALL);
    cudaFuncSetAttribute(hgemm<false, false,1>, cudaFuncAttributeMaxDynamicSharedMemorySize, SMEM_SMALL);
    cudaFuncSetAttribute(hgemm_big<1>, cudaFuncAttributeMaxDynamicSharedMemorySize, BIG_SMEM);
    cudaFuncSetAttribute(hgemm_big<0>, cudaFuncAttributeMaxDynamicSharedMemorySize, BIG_SMEM);

    const float scale = 0.08838834764831843f;  // 1/sqrt(128)

    // 0) fp32 -> fp16
    f2h_all<<<(N4_VX + N4_WQ + N4_WKV + N4_WQ) / 256, 256>>>(
        Vx, Wq, Wkv, Wp, hVx, hWq, hWkv, hWp);
    f2h_pad77<<<NB * CC, 128>>>(Tx, hTx, NB * CC);

    // 1) KV = Wkv @ Tx + bkv : M=2048, N=80(valid 77), K=1024, per-b
    hgemm<false, true, 1><<<dim3(1, 16, NB), 256, SMEM_SMALL>>>(
        hWkv, hTx, hKV, bkv, 2048, TP, CC,
        CC, TP, TP,
        0, 0, (long long)CC * TP, 0,
        (long long)2 * CC * TP, 0, 1, 1.0f, CC, TP, TT);

    // 2) Q = Wq @ Vx + bq : M=1024, N=1024, K=1024, per-b  [BIG bulk]
    hgemm_big<1><<<dim3(8, 4, NB), 256, BIG_SMEM>>>(
        hWq, hVx, hQ, bq, (long long)CC * NN, (long long)CC * NN);

    // 3) P = softmax(scale * Q_h^T K_h) : M=1024(n), N=77(t), K=128, per-(b,h)
    hgemm<true, true, 2><<<dim3(1, 8, NB * NH), 256, SMEM_SMALL>>>(
        hQ, hKV, hP, nullptr, NN, TT, HD,
        NN, TP, TP,
        (long long)CC * NN, (long long)HD * NN,
        (long long)2 * CC * TP, (long long)2 * HD * TP,
        (long long)NH * NN * TP, (long long)NN * TP,
        NH, scale, HD, TP, TT);

    // 4) O = V_h @ P^T : M=128(d), N=1024(n), K=77, per-(b,h)
    hgemm<false, false, 1><<<dim3(8, 1, NB * NH), 256, SMEM_SMALL>>>(
        hKV + (size_t)HD * TP, hP, hO, nullptr, HD, NN, TT,
        TP, TP, NN,
        (long long)2 * CC * TP, (long long)2 * HD * TP,
        (long long)NH * NN * TP, (long long)NN * TP,
        (long long)CC * NN, (long long)HD * NN,
        NH, 1.0f, TP, TP, NN);

    // 5) Y = Wp @ O + bp : M=1024, N=1024, K=1024, per-b, fp32 out  [BIG bulk]
    hgemm_big<0><<<dim3(8, 4, NB), 256, BIG_SMEM>>>(
        hWp, hO, Y, bp, (long long)CC * NN, (long long)CC * NN);
}

// round 13
// speedup vs baseline: 1.0705x; 1.0705x over previous
#include <cuda_runtime.h>
#include <cuda_fp16.h>
#include <cstdint>

// ---------------------------------------------------------------------------
// B=16, C=1024, N=1024, T=77(pad 80), heads=8, hd=128.
//   big GEMMs (Q, Y): 256x128x32, 512 thr (round-8 config, best measured)
//   KV: 128x128x32 small GEMM
//   attention: ONE fused kernel  S=Q^T K -> softmax -> O=V P^T  (P in smem)
// Scratch fp16; cols 77..79 stored zero.
// KV head split: K_h rows [256h,256h+128), V_h rows [256h+128,256h+256).
// ---------------------------------------------------------------------------

#define NB 16
#define CC 1024
#define NN 1024
#define TT 77
#define TP 80
#define NH 8
#define HD 128

__device__ __half h_Vx[(size_t)NB * CC * NN];
__device__ __half h_Tx[(size_t)NB * CC * TP];
__device__ __half h_Wq[(size_t)CC * CC];
__device__ __half h_Wkv[(size_t)2 * CC * CC];
__device__ __half h_Wp[(size_t)CC * CC];
__device__ __half h_Q [(size_t)NB * CC * NN];
__device__ __half h_KV[(size_t)NB * 2 * CC * TP];
__device__ __half h_O [(size_t)NB * CC * NN];

__device__ __forceinline__ uint32_t smem_u32(const void* p) {
    uint32_t a;
    asm("{ .reg .u64 t; cvta.to.shared.u64 t, %1; cvt.u32.u64 %0, t; }" : "=r"(a) : "l"(p));
    return a;
}
#define CP16(d, s, sz) asm volatile("cp.async.cg.shared.global [%0], [%1], 16, %2;" :: "r"(d), "l"(s), "r"(sz) : "memory")
#define CP_COMMIT()    asm volatile("cp.async.commit_group;" ::: "memory")
#define CP_WAIT1()     asm volatile("cp.async.wait_group 1;" ::: "memory")
#define CP_WAIT0()     asm volatile("cp.async.wait_group 0;" ::: "memory")

#define LDSM_X4(r0, r1, r2, r3, a) \
    asm volatile("ldmatrix.sync.aligned.m8n8.x4.shared.b16 {%0,%1,%2,%3}, [%4];" \
        : "=r"(r0), "=r"(r1), "=r"(r2), "=r"(r3) : "r"(a))
#define LDSM_X4T(r0, r1, r2, r3, a) \
    asm volatile("ldmatrix.sync.aligned.m8n8.x4.trans.shared.b16 {%0,%1,%2,%3}, [%4];" \
        : "=r"(r0), "=r"(r1), "=r"(r2), "=r"(r3) : "r"(a))

__device__ __forceinline__ void mma_f16(float* c, const uint32_t* a, const uint32_t* b) {
    asm volatile(
        "mma.sync.aligned.m16n8k16.row.col.f32.f16.f16.f32 "
        "{%0,%1,%2,%3}, {%4,%5,%6,%7}, {%8,%9}, {%0,%1,%2,%3};\n"
        : "+f"(c[0]), "+f"(c[1]), "+f"(c[2]), "+f"(c[3])
        : "r"(a[0]), "r"(a[1]), "r"(a[2]), "r"(a[3]), "r"(b[0]), "r"(b[1]));
}

// ===========================================================================
// BIG GEMM (round-8 config): 256x128x32, 512 thr = 16 warps (4m x 4n),
// warp tile 64x32.  OM: 0 = fp32 out, 1 = fp16 out.
// ===========================================================================
#define BIG_A_B 20480                      // 256*40*2
#define BIG_B_B 8704                       // 32*136*2
#define BIG_STAGE (BIG_A_B + BIG_B_B)      // 29184
#define BIG_SMEM (BIG_STAGE * 3)           // 87552

template <int OM>
__global__ __launch_bounds__(512, 1)
void hgemm_big(const __half* __restrict__ A, const __half* __restrict__ B,
               void* __restrict__ Cv, const float* __restrict__ bias,
               long long sBb, long long sCb)
{
    extern __shared__ char smem[];
    const uint32_t sb = smem_u32(smem);

    const int tid  = threadIdx.x;
    const int lane = tid & 31;
    const int warp = tid >> 5;
    const int wm = (warp & 3) * 64;
    const int wn = (warp >> 2) * 32;
    const int gid = lane >> 2;
    const int tig = lane & 3;
    const int tl  = lane >> 3;
    const int rr  = lane & 7;

    const int m0 = blockIdx.y * 256;
    const int n0 = blockIdx.x * 128;
    const __half* Bb = B + (size_t)blockIdx.z * sBb;

    auto load_tile = [&](int kt, int s) {
        const int k0 = kt << 5;
        const uint32_t aB = sb + (uint32_t)s * BIG_STAGE;
        const uint32_t bB = aB + BIG_A_B;
        #pragma unroll
        for (int i = 0; i < 2; i++) {                    // A: 256m x 32k
            int sg = tid + i * 512;
            int m = sg >> 2, sk = sg & 3;
            CP16(aB + (uint32_t)(m * 40 + sk * 8) * 2,
                 A + (size_t)(m0 + m) * CC + k0 + sk * 8, 16);
        }
        {                                                // B: 32k x 128n
            int k = tid >> 4, sn = tid & 15;
            CP16(bB + (uint32_t)(k * 136 + sn * 8) * 2,
                 Bb + (size_t)(k0 + k) * NN + n0 + sn * 8, 16);
        }
        CP_COMMIT();
    };

    float acc[4][4][4];
    #pragma unroll
    for (int mi = 0; mi < 4; mi++)
        #pragma unroll
        for (int ni = 0; ni < 4; ni++)
            #pragma unroll
            for (int j = 0; j < 4; j++) acc[mi][ni][j] = 0.f;

    load_tile(0, 0);
    load_tile(1, 1);

    const int nkt = CC >> 5;
    for (int kt = 0; kt < nkt; kt++) {
        CP_WAIT1();
        __syncthreads();
        if (kt + 2 < nkt) load_tile(kt + 2, (kt + 2) % 3);
        else CP_COMMIT();

        const uint32_t aB = sb + (uint32_t)((kt % 3) * BIG_STAGE);
        const uint32_t bB = aB + BIG_A_B;

        #pragma unroll
        for (int kk = 0; kk < 32; kk += 16) {
            uint32_t afr[4][4], bfr[4][2];
            #pragma unroll
            for (int mi = 0; mi < 4; mi++) {
                uint32_t addr = aB + (uint32_t)((wm + mi * 16 + (tl & 1) * 8 + rr) * 40
                                                + kk + (tl >> 1) * 8) * 2;
                LDSM_X4(afr[mi][0], afr[mi][1], afr[mi][2], afr[mi][3], addr);
            }
            #pragma unroll
            for (int np = 0; np < 2; np++) {
                uint32_t addr = bB + (uint32_t)((kk + (tl & 1) * 8 + rr) * 136
                                                + wn + np * 16 + (tl >> 1) * 8) * 2;
                LDSM_X4T(bfr[2*np][0], bfr[2*np][1], bfr[2*np+1][0], bfr[2*np+1][1], addr);
            }
            #pragma unroll
            for (int mi = 0; mi < 4; mi++)
                #pragma unroll
                for (int ni = 0; ni < 4; ni++)
                    mma_f16(acc[mi][ni], afr[mi], bfr[ni]);
        }
    }

    #pragma unroll
    for (int mi = 0; mi < 4; mi++) {
        int r0 = m0 + wm + mi * 16 + gid;
        float bv0 = bias[r0];
        float bv1 = bias[r0 + 8];
        #pragma unroll
        for (int ni = 0; ni < 4; ni++) {
            int c0 = n0 + wn + ni * 8 + 2 * tig;
            if (OM == 0) {
                float* Cb = (float*)Cv + (size_t)blockIdx.z * sCb;
                Cb[(size_t)r0 * NN + c0]           = acc[mi][ni][0] + bv0;
                Cb[(size_t)r0 * NN + c0 + 1]       = acc[mi][ni][1] + bv0;
                Cb[(size_t)(r0 + 8) * NN + c0]     = acc[mi][ni][2] + bv1;
                Cb[(size_t)(r0 + 8) * NN + c0 + 1] = acc[mi][ni][3] + bv1;
            } else {
                __half* Cb = (__half*)Cv + (size_t)blockIdx.z * sCb;
                Cb[(size_t)r0 * NN + c0]           = __float2half(acc[mi][ni][0] + bv0);
                Cb[(size_t)r0 * NN + c0 + 1]       = __float2half(acc[mi][ni][1] + bv0);
                Cb[(size_t)(r0 + 8) * NN + c0]     = __float2half(acc[mi][ni][2] + bv1);
                Cb[(size_t)(r0 + 8) * NN + c0 + 1] = __float2half(acc[mi][ni][3] + bv1);
            }
        }
    }
}

// ===========================================================================
// FUSED ATTENTION: one CTA = one (b,h), one 128-pixel n-tile.
//   S[n][t] = scale * sum_d Q[d][n] K[d][t]   (d=128, t=80 incl. zero pad)
//   P = softmax_t(S)  (t in [0,77); cols 77..79 forced 0), P kept in smem
//   O[d][n] = sum_t V[d][t] P[n][t]
// smem: sQ [128d][136n pitch]h | sK/sP [128][80]h | sV [128][80]h | sS [128][84]f
// ===========================================================================
#define FA_SQ 0
#define FA_SK 34816
#define FA_SV 55296
#define FA_SS 75776
#define FA_SMEM 118784

__global__ __launch_bounds__(256, 1)
void fused_attn(const __half* __restrict__ Q, const __half* __restrict__ KV,
                __half* __restrict__ O, float scale)
{
    extern __shared__ char smem[];
    const uint32_t sb = smem_u32(smem);

    const int tid  = threadIdx.x;
    const int lane = tid & 31;
    const int warp = tid >> 5;
    const int gid = lane >> 2;
    const int tig = lane & 3;
    const int tl  = lane >> 3;
    const int rr  = lane & 7;

    const int n0 = blockIdx.x * 128;
    const int z = blockIdx.y;           // b*8 + h
    const int b = z >> 3, h = z & 7;

    const __half* Qb = Q  + (size_t)b * CC * NN + (size_t)(h * HD) * NN;
    const __half* Kb = KV + (size_t)b * 2 * CC * TP + (size_t)(2 * HD * h) * TP;
    const __half* Vb = Kb + (size_t)HD * TP;

    // ---- load Q tile, K, V ----
    #pragma unroll
    for (int i = 0; i < 8; i++) {       // Q: 128d x 128n
        int c = tid + i * 256;
        int d = c >> 4, o = (c & 15) * 8;
        CP16(sb + FA_SQ + (uint32_t)(d * 136 + o) * 2,
             Qb + (size_t)d * NN + n0 + o, 16);
    }
    #pragma unroll
    for (int i = 0; i < 5; i++) {       // K: 128d x 80t
        int c = tid + i * 256;
        int d = c / 10, o = (c % 10) * 8;
        CP16(sb + FA_SK + (uint32_t)(d * 80 + o) * 2,
             Kb + (size_t)d * TP + o, 16);
    }
    #pragma unroll
    for (int i = 0; i < 5; i++) {       // V: 128d x 80t
        int c = tid + i * 256;
        int d = c / 10, o = (c % 10) * 8;
        CP16(sb + FA_SV + (uint32_t)(d * 80 + o) * 2,
             Vb + (size_t)d * TP + o, 16);
    }
    CP_COMMIT();
    CP_WAIT0();
    __syncthreads();

    // ---- S = Q^T K : warp owns 16 n-rows [warp*16, +16), all 80 t-cols ----
    {
        const int wm = warp * 16;
        float accs[10][4];
        #pragma unroll
        for (int ni = 0; ni < 10; ni++)
            #pragma unroll
            for (int j = 0; j < 4; j++) accs[ni][j] = 0.f;

        #pragma unroll
        for (int kk = 0; kk < 128; kk += 16) {
            uint32_t afr[4];
            uint32_t aaddr = sb + FA_SQ + (uint32_t)((kk + (tl >> 1) * 8 + rr) * 136
                                                     + wm + (tl & 1) * 8) * 2;
            LDSM_X4T(afr[0], afr[1], afr[2], afr[3], aaddr);
            uint32_t bfr[10][2];
            #pragma unroll
            for (int tb = 0; tb < 5; tb++) {
                uint32_t baddr = sb + FA_SK + (uint32_t)((kk + (tl & 1) * 8 + rr) * 80
                                                         + tb * 16 + (tl >> 1) * 8) * 2;
                LDSM_X4T(bfr[2*tb][0], bfr[2*tb][1], bfr[2*tb+1][0], bfr[2*tb+1][1], baddr);
            }
            #pragma unroll
            for (int ni = 0; ni < 10; ni++)
                mma_f16(accs[ni], afr, bfr[ni]);
        }

        // stage scaled S rows to sS
        float* st = (float*)(smem + FA_SS);
        #pragma unroll
        for (int ni = 0; ni < 10; ni++) {
            int c0 = ni * 8 + 2 * tig;
            st[(wm + gid) * 84 + c0]         = scale * accs[ni][0];
            st[(wm + gid) * 84 + c0 + 1]     = scale * accs[ni][1];
            st[(wm + gid + 8) * 84 + c0]     = scale * accs[ni][2];
            st[(wm + gid + 8) * 84 + c0 + 1] = scale * accs[ni][3];
        }
        __syncthreads();   // all warps done reading sK; staging complete

        // softmax per row; write P (fp16) into sK region, cols>=77 -> 0
        __half* P = (__half*)(smem + FA_SK);
        for (int i = 0; i < 16; i++) {
            float* row = st + (wm + i) * 84;
            float x0 = row[lane];
            float x1 = row[lane + 32];
            float x2 = (lane + 64 < TT) ? row[lane + 64] : -1e30f;
            float m = fmaxf(x0, fmaxf(x1, x2));
            #pragma unroll
            for (int off = 16; off > 0; off >>= 1)
                m = fmaxf(m, __shfl_xor_sync(0xFFFFFFFFu, m, off));
            float e0 = __expf(x0 - m);
            float e1 = __expf(x1 - m);
            float e2 = (lane + 64 < TT) ? __expf(x2 - m) : 0.f;
            float s = e0 + e1 + e2;
            #pragma unroll
            for (int off = 16; off > 0; off >>= 1)
                s += __shfl_xor_sync(0xFFFFFFFFu, s, off);
            float inv = 1.f / s;
            __half* dst = P + (wm + i) * 80;
            dst[lane]      = __float2half(e0 * inv);
            dst[lane + 32] = __float2half(e1 * inv);
            if (lane + 64 < TP)
                dst[lane + 64] = __float2half((lane + 64 < TT) ? e2 * inv : 0.f);
        }
    }
    __syncthreads();

    // ---- O = V P^T : warps 4m(d) x 2n(pixels), warp tile 32x64, K=80 ----
    {
        const int wm2 = (warp & 3) * 32;
        const int wn2 = (warp >> 2) * 64;
        float acco[2][8][4];
        #pragma unroll
        for (int mi = 0; mi < 2; mi++)
            #pragma unroll
            for (int ni = 0; ni < 8; ni++)
                #pragma unroll
                for (int j = 0; j < 4; j++) acco[mi][ni][j] = 0.f;

        #pragma unroll
        for (int kk = 0; kk < 80; kk += 16) {
            uint32_t afr[2][4], bfr[8][2];
            #pragma unroll
            for (int mi = 0; mi < 2; mi++) {
                uint32_t addr = sb + FA_SV + (uint32_t)((wm2 + mi * 16 + (tl & 1) * 8 + rr) * 80
                                                        + kk + (tl >> 1) * 8) * 2;
                LDSM_X4(afr[mi][0], afr[mi][1], afr[mi][2], afr[mi][3], addr);
            }
            #pragma unroll
            for (int np = 0; np < 4; np++) {
                uint32_t addr = sb + FA_SK + (uint32_t)((wn2 + np * 16 + (tl >> 1) * 8 + rr) * 80
                                                        + kk + (tl & 1) * 8) * 2;
                LDSM_X4(bfr[2*np][0], bfr[2*np][1], bfr[2*np+1][0], bfr[2*np+1][1], addr);
            }
            #pragma unroll
            for (int mi = 0; mi < 2; mi++)
                #pragma unroll
                for (int ni = 0; ni < 8; ni++)
                    mma_f16(acco[mi][ni], afr[mi], bfr[ni]);
        }

        __half* Ob = O + (size_t)b * CC * NN + (size_t)(h * HD) * NN;
        #pragma unroll
        for (int mi = 0; mi < 2; mi++) {
            int r0 = wm2 + mi * 16 + gid;
            #pragma unroll
            for (int ni = 0; ni < 8; ni++) {
                int c0 = n0 + wn2 + ni * 8 + 2 * tig;
                Ob[(size_t)r0 * NN + c0]           = __float2half(acco[mi][ni][0]);
                Ob[(size_t)r0 * NN + c0 + 1]       = __float2half(acco[mi][ni][1]);
                Ob[(size_t)(r0 + 8) * NN + c0]     = __float2half(acco[mi][ni][2]);
                Ob[(size_t)(r0 + 8) * NN + c0 + 1] = __float2half(acco[mi][ni][3]);
            }
        }
    }
}

// ===========================================================================
// Small generic GEMM — KV projection only (unchanged machinery).
// ===========================================================================
#define STAGE_B 20480

template <bool AT, bool BT, int OM>
__global__ __launch_bounds__(256, 2)
void hgemm(const __half* __restrict__ A, const __half* __restrict__ B,
           void* __restrict__ Cv, const float* __restrict__ bias,
           int M, int N, int K,
           long long sA, long long sB, long long ldc,
           long long sAb, long long sAh, long long sBb, long long sBh,
           long long sCb, long long sCh, int nh, float alpha,
           int Ka, int Bbound, int nvalid)
{
    extern __shared__ char smem[];
    const uint32_t sb = smem_u32(smem);

    const int tid  = threadIdx.x;
    const int lane = tid & 31;
    const int warp = tid >> 5;
    const int wm = (warp & 3) * 32;
    const int wn = (warp >> 2) * 64;
    const int gid = lane >> 2;
    const int tig = lane & 3;
    const int tl  = lane >> 3;
    const int rr  = lane & 7;

    const int z = blockIdx.z;
    const int b = z / nh;
    const int h = z - b * nh;
    const __half* Ab = A + (size_t)b * sAb + (size_t)h * sAh;
    const __half* Bb = B + (size_t)b * sBb + (size_t)h * sBh;

    const int m0 = blockIdx.y * 128;
    const int n0 = blockIdx.x * 128;
    const int nkt = (K + 31) >> 5;

    auto load_tile = [&](int kt, int s) {
        const int k0 = kt << 5;
        const uint32_t aB = sb + (uint32_t)s * STAGE_B;
        const uint32_t bB = aB + 10240;
        #pragma unroll
        for (int i = 0; i < 2; i++) {
            int sg = tid + i * 256;
            if (!AT) {
                int m = sg >> 2, sk = sg & 3;
                CP16(aB + (uint32_t)(m * 40 + sk * 8) * 2,
                     Ab + (size_t)(m0 + m) * sA + k0 + sk * 8,
                     (k0 + sk * 8 < Ka) ? 16 : 0);
            } else {
                int k = sg >> 4, sm = sg & 15;
                CP16(aB + (uint32_t)(k * 136 + sm * 8) * 2,
                     Ab + (size_t)(k0 + k) * sA + m0 + sm * 8, 16);
            }
        }
        #pragma unroll
        for (int i = 0; i < 2; i++) {
            int sg = tid + i * 256;
            if (BT) {
                int k = sg >> 4, sn = sg & 15;
                CP16(bB + (uint32_t)(k * 136 + sn * 8) * 2,
                     Bb + (size_t)(k0 + k) * sB + n0 + sn * 8,
                     (n0 + sn * 8 < Bbound) ? 16 : 0);
            } else {
                int n = sg >> 2, sk = sg & 3;
                CP16(bB + (uint32_t)(n * 40 + sk * 8) * 2,
                     Bb + (size_t)(n0 + n) * sB + k0 + sk * 8,
                     (k0 + sk * 8 < Bbound) ? 16 : 0);
            }
        }
        CP_COMMIT();
    };

    float acc[2][8][4];
    #pragma unroll
    for (int mi = 0; mi < 2; mi++)
        #pragma unroll
        for (int ni = 0; ni < 8; ni++)
            #pragma unroll
            for (int j = 0; j < 4; j++) acc[mi][ni][j] = 0.f;

    load_tile(0, 0);
    if (nkt > 1) load_tile(1, 1); else CP_COMMIT();

    for (int kt = 0; kt < nkt; kt++) {
        CP_WAIT1();
        __syncthreads();
        if (kt + 2 < nkt) load_tile(kt + 2, (kt + 2) % 3);
        else CP_COMMIT();

        const uint32_t aB = sb + (uint32_t)((kt % 3) * STAGE_B);
        const uint32_t bB = aB + 10240;

        #pragma unroll
        for (int kk = 0; kk < 32; kk += 16) {
            uint32_t afr[2][4], bfr[8][2];
            #pragma unroll
            for (int mi = 0; mi < 2; mi++) {
                uint32_t addr;
                if (!AT)
                    addr = aB + (uint32_t)((wm + mi * 16 + (tl & 1) * 8 + rr) * 40
                                           + kk + (tl >> 1) * 8) * 2;
                else
                    addr = aB + (uint32_t)((kk + (tl >> 1) * 8 + rr) * 136
                                           + wm + mi * 16 + (tl & 1) * 8) * 2;
                if (!AT) LDSM_X4 (afr[mi][0], afr[mi][1], afr[mi][2], afr[mi][3], addr);
                else     LDSM_X4T(afr[mi][0], afr[mi][1], afr[mi][2], afr[mi][3], addr);
            }
            #pragma unroll
            for (int np = 0; np < 4; np++) {
                int nb = wn + np * 16;
                uint32_t addr;
                if (BT)
                    addr = bB + (uint32_t)((kk + (tl & 1) * 8 + rr) * 136
                                           + nb + (tl >> 1) * 8) * 2;
                else
                    addr = bB + (uint32_t)((nb + (tl >> 1) * 8 + rr) * 40
                                           + kk + (tl & 1) * 8) * 2;
                if (BT) LDSM_X4T(bfr[2*np][0], bfr[2*np][1], bfr[2*np+1][0], bfr[2*np+1][1], addr);
                else    LDSM_X4 (bfr[2*np][0], bfr[2*np][1], bfr[2*np+1][0], bfr[2*np+1][1], addr);
            }
            #pragma unroll
            for (int mi = 0; mi < 2; mi++)
                #pragma unroll
                for (int ni = 0; ni < 8; ni++)
                    mma_f16(acc[mi][ni], afr[mi], bfr[ni]);
        }
    }

    if (OM == 1) {
        __half* Cb = (__half*)Cv + (size_t)b * sCb + (size_t)h * sCh;
        #pragma unroll
        for (int mi = 0; mi < 2; mi++) {
            int r0 = m0 + wm + mi * 16 + gid;
            float bv0 = bias ? bias[r0]     : 0.f;
            float bv1 = bias ? bias[r0 + 8] : 0.f;
            #pragma unroll
            for (int ni = 0; ni < 8; ni++) {
                int c0 = n0 + wn + ni * 8 + 2 * tig;
                if (c0 < N) {
                    #pragma unroll
                    for (int j = 0; j < 2; j++) {
                        int c = c0 + j;
                        bool v = (c < nvalid);
                        Cb[(size_t)r0 * ldc + c] =
                            __float2half(v ? alpha * acc[mi][ni][j] + bv0 : 0.f);
                        Cb[(size_t)(r0 + 8) * ldc + c] =
                            __float2half(v ? alpha * acc[mi][ni][2 + j] + bv1 : 0.f);
                    }
                }
            }
        }
    }
}

// ---------------------------------------------------------------- converters
#define N4_VX  (NB * CC * NN / 4)
#define N4_WQ  (CC * CC / 4)
#define N4_WKV (2 * CC * CC / 4)

__global__ void f2h_all(const float* __restrict__ Vx, const float* __restrict__ Wq,
                        const float* __restrict__ Wkv, const float* __restrict__ Wp,
                        __half* __restrict__ dVx, __half* __restrict__ dWq,
                        __half* __restrict__ dWkv, __half* __restrict__ dWp)
{
    int i = blockIdx.x * 256 + threadIdx.x;
    const float* s; __half* d; int j;
    if (i < N4_VX)                       { s = Vx;  d = dVx;  j = i; }
    else if (i < N4_VX + N4_WQ)          { s = Wq;  d = dWq;  j = i - N4_VX; }
    else if (i < N4_VX + N4_WQ + N4_WKV) { s = Wkv; d = dWkv; j = i - N4_VX - N4_WQ; }
    else                                 { s = Wp;  d = dWp;  j = i - N4_VX - N4_WQ - N4_WKV; }
    float4 v = reinterpret_cast<const float4*>(s)[j];
    __half2* d2 = reinterpret_cast<__half2*>(d);
    d2[2 * j]     = __floats2half2_rn(v.x, v.y);
    d2[2 * j + 1] = __floats2half2_rn(v.z, v.w);
}
__global__ void f2h_pad77(const float* __restrict__ s, __half* __restrict__ d, int rows)
{
    int r = blockIdx.x, c = threadIdx.x;
    if (c < TP)
        d[(size_t)r * TP + c] = __float2half((c < TT) ? s[(size_t)r * TT + c] : 0.f);
}

// ---------------------------------------------------------------- launch
extern "C" void kernel_launch(void* const* d_in, const int* in_sizes, int n_in,
                              void* d_out, int out_size)
{
    const float* Vx  = (const float*)d_in[0];
    const float* Tx  = (const float*)d_in[1];
    const float* Wq  = (const float*)d_in[2];
    const float* bq  = (const float*)d_in[3];
    const float* Wkv = (const float*)d_in[4];
    const float* bkv = (const float*)d_in[5];
    const float* Wp  = (const float*)d_in[6];
    const float* bp  = (const float*)d_in[7];
    float* Y = (float*)d_out;

    __half *hVx, *hTx, *hWq, *hWkv, *hWp, *hQ, *hKV, *hO;
    cudaGetSymbolAddress((void**)&hVx, h_Vx);
    cudaGetSymbolAddress((void**)&hTx, h_Tx);
    cudaGetSymbolAddress((void**)&hWq, h_Wq);
    cudaGetSymbolAddress((void**)&hWkv, h_Wkv);
    cudaGetSymbolAddress((void**)&hWp, h_Wp);
    cudaGetSymbolAddress((void**)&hQ,  h_Q);
    cudaGetSymbolAddress((void**)&hKV, h_KV);
    cudaGetSymbolAddress((void**)&hO,  h_O);

    constexpr int SMEM_SMALL = STAGE_B * 3;   // 61440
    cudaFuncSetAttribute(hgemm<false, true, 1>, cudaFuncAttributeMaxDynamicSharedMemorySize, SMEM_SMALL);
    cudaFuncSetAttribute(hgemm_big<1>, cudaFuncAttributeMaxDynamicSharedMemorySize, BIG_SMEM);
    cudaFuncSetAttribute(hgemm_big<0>, cudaFuncAttributeMaxDynamicSharedMemorySize, BIG_SMEM);
    cudaFuncSetAttribute(fused_attn, cudaFuncAttributeMaxDynamicSharedMemorySize, FA_SMEM);

    const float scale = 0.08838834764831843f;  // 1/sqrt(128)

    // 0) fp32 -> fp16
    f2h_all<<<(N4_VX + N4_WQ + N4_WKV + N4_WQ) / 256, 256>>>(
        Vx, Wq, Wkv, Wp, hVx, hWq, hWkv, hWp);
    f2h_pad77<<<NB * CC, 128>>>(Tx, hTx, NB * CC);

    // 1) KV = Wkv @ Tx + bkv : M=2048, N=80(valid 77), K=1024, per-b
    hgemm<false, true, 1><<<dim3(1, 16, NB), 256, SMEM_SMALL>>>(
        hWkv, hTx, hKV, bkv, 2048, TP, CC,
        CC, TP, TP,
        0, 0, (long long)CC * TP, 0,
        (long long)2 * CC * TP, 0, 1, 1.0f, CC, TP, TT);

    // 2) Q = Wq @ Vx + bq : M=1024, N=1024, K=1024, per-b  [BIG]
    hgemm_big<1><<<dim3(8, 4, NB), 512, BIG_SMEM>>>(
        hWq, hVx, hQ, bq, (long long)CC * NN, (long long)CC * NN);

    // 3) fused attention: S -> softmax -> O, per (b,h) x n-tile
    fused_attn<<<dim3(8, NB * NH), 256, FA_SMEM>>>(hQ, hKV, hO, scale);

    // 4) Y = Wp @ O + bp : M=1024, N=1024, K=1024, per-b, fp32 out  [BIG]
    hgemm_big<0><<<dim3(8, 4, NB), 512, BIG_SMEM>>>(
        hWp, hO, Y, bp, (long long)CC * NN, (long long)CC * NN);
}

// round 14
// speedup vs baseline: 1.9309x; 1.8037x over previous
#include <cuda_runtime.h>
#include <cuda_fp16.h>
#include <cstdint>

// ---------------------------------------------------------------------------
// B=16, C=1024, N=1024, T=77(pad 80), heads=8, hd=128.
//   big GEMMs (Q, Y): 256x128x64 tiles, 512 thr, 16 warps (4m x 4n) 64x32
//     (BK=64: half the barriers, 2-tile ~4096-cyc latency cover)
//   KV: 128x128x32 small GEMM
//   fused attention: S=Q^T K -> quad-shuffle softmax in registers -> O=V P^T
//     (P in smem, no fp32 staging; 75.8KB smem -> 2 CTAs/SM)
// Scratch fp16; cols 77..79 stored zero.
// KV head split: K_h rows [256h,256h+128), V_h rows [256h+128,256h+256).
// ---------------------------------------------------------------------------

#define NB 16
#define CC 1024
#define NN 1024
#define TT 77
#define TP 80
#define NH 8
#define HD 128

__device__ __half h_Vx[(size_t)NB * CC * NN];
__device__ __half h_Tx[(size_t)NB * CC * TP];
__device__ __half h_Wq[(size_t)CC * CC];
__device__ __half h_Wkv[(size_t)2 * CC * CC];
__device__ __half h_Wp[(size_t)CC * CC];
__device__ __half h_Q [(size_t)NB * CC * NN];
__device__ __half h_KV[(size_t)NB * 2 * CC * TP];
__device__ __half h_O [(size_t)NB * CC * NN];

__device__ __forceinline__ uint32_t smem_u32(const void* p) {
    uint32_t a;
    asm("{ .reg .u64 t; cvta.to.shared.u64 t, %1; cvt.u32.u64 %0, t; }" : "=r"(a) : "l"(p));
    return a;
}
#define CP16(d, s, sz) asm volatile("cp.async.cg.shared.global [%0], [%1], 16, %2;" :: "r"(d), "l"(s), "r"(sz) : "memory")
#define CP_COMMIT()    asm volatile("cp.async.commit_group;" ::: "memory")
#define CP_WAIT1()     asm volatile("cp.async.wait_group 1;" ::: "memory")
#define CP_WAIT0()     asm volatile("cp.async.wait_group 0;" ::: "memory")

#define LDSM_X4(r0, r1, r2, r3, a) \
    asm volatile("ldmatrix.sync.aligned.m8n8.x4.shared.b16 {%0,%1,%2,%3}, [%4];" \
        : "=r"(r0), "=r"(r1), "=r"(r2), "=r"(r3) : "r"(a))
#define LDSM_X4T(r0, r1, r2, r3, a) \
    asm volatile("ldmatrix.sync.aligned.m8n8.x4.trans.shared.b16 {%0,%1,%2,%3}, [%4];" \
        : "=r"(r0), "=r"(r1), "=r"(r2), "=r"(r3) : "r"(a))

__device__ __forceinline__ void mma_f16(float* c, const uint32_t* a, const uint32_t* b) {
    asm volatile(
        "mma.sync.aligned.m16n8k16.row.col.f32.f16.f16.f32 "
        "{%0,%1,%2,%3}, {%4,%5,%6,%7}, {%8,%9}, {%0,%1,%2,%3};\n"
        : "+f"(c[0]), "+f"(c[1]), "+f"(c[2]), "+f"(c[3])
        : "r"(a[0]), "r"(a[1]), "r"(a[2]), "r"(a[3]), "r"(b[0]), "r"(b[1]));
}

// ===========================================================================
// BIG GEMM: 256x128x64, 512 thr = 16 warps (4m x 4n), warp tile 64x32.
// A [m][72]h pitch (144B, conflict-free), B [k][136]h pitch (272B, c-free).
// OM: 0 = fp32 out, 1 = fp16 out.
// ===========================================================================
#define BIG_A_B 36864                      // 256*72*2
#define BIG_B_B 17408                      // 64*136*2
#define BIG_STAGE (BIG_A_B + BIG_B_B)      // 54272
#define BIG_SMEM (BIG_STAGE * 3)           // 162816

template <int OM>
__global__ __launch_bounds__(512, 1)
void hgemm_big(const __half* __restrict__ A, const __half* __restrict__ B,
               void* __restrict__ Cv, const float* __restrict__ bias,
               long long sBb, long long sCb)
{
    extern __shared__ char smem[];
    const uint32_t sb = smem_u32(smem);

    const int tid  = threadIdx.x;
    const int lane = tid & 31;
    const int warp = tid >> 5;
    const int wm = (warp & 3) * 64;
    const int wn = (warp >> 2) * 32;
    const int gid = lane >> 2;
    const int tig = lane & 3;
    const int tl  = lane >> 3;
    const int rr  = lane & 7;

    const int m0 = blockIdx.y * 256;
    const int n0 = blockIdx.x * 128;
    const __half* Bb = B + (size_t)blockIdx.z * sBb;

    auto load_tile = [&](int kt, int s) {
        const int k0 = kt << 6;
        const uint32_t aB = sb + (uint32_t)s * BIG_STAGE;
        const uint32_t bB = aB + BIG_A_B;
        #pragma unroll
        for (int i = 0; i < 4; i++) {                    // A: 256m x 64k
            int sg = tid + i * 512;
            int m = sg >> 3, seg = sg & 7;
            CP16(aB + (uint32_t)(m * 72 + seg * 8) * 2,
                 A + (size_t)(m0 + m) * CC + k0 + seg * 8, 16);
        }
        #pragma unroll
        for (int i = 0; i < 2; i++) {                    // B: 64k x 128n
            int sg = tid + i * 512;
            int k = sg >> 4, sn = sg & 15;
            CP16(bB + (uint32_t)(k * 136 + sn * 8) * 2,
                 Bb + (size_t)(k0 + k) * NN + n0 + sn * 8, 16);
        }
        CP_COMMIT();
    };

    float acc[4][4][4];
    #pragma unroll
    for (int mi = 0; mi < 4; mi++)
        #pragma unroll
        for (int ni = 0; ni < 4; ni++)
            #pragma unroll
            for (int j = 0; j < 4; j++) acc[mi][ni][j] = 0.f;

    load_tile(0, 0);
    load_tile(1, 1);

    const int nkt = CC >> 6;                 // 16
    for (int kt = 0; kt < nkt; kt++) {
        CP_WAIT1();
        __syncthreads();
        if (kt + 2 < nkt) load_tile(kt + 2, (kt + 2) % 3);
        else CP_COMMIT();

        const uint32_t aB = sb + (uint32_t)((kt % 3) * BIG_STAGE);
        const uint32_t bB = aB + BIG_A_B;

        #pragma unroll
        for (int kk = 0; kk < 64; kk += 16) {
            uint32_t afr[4][4], bfr[4][2];
            #pragma unroll
            for (int mi = 0; mi < 4; mi++) {
                uint32_t addr = aB + (uint32_t)((wm + mi * 16 + (tl & 1) * 8 + rr) * 72
                                                + kk + (tl >> 1) * 8) * 2;
                LDSM_X4(afr[mi][0], afr[mi][1], afr[mi][2], afr[mi][3], addr);
            }
            #pragma unroll
            for (int np = 0; np < 2; np++) {
                uint32_t addr = bB + (uint32_t)((kk + (tl & 1) * 8 + rr) * 136
                                                + wn + np * 16 + (tl >> 1) * 8) * 2;
                LDSM_X4T(bfr[2*np][0], bfr[2*np][1], bfr[2*np+1][0], bfr[2*np+1][1], addr);
            }
            #pragma unroll
            for (int mi = 0; mi < 4; mi++)
                #pragma unroll
                for (int ni = 0; ni < 4; ni++)
                    mma_f16(acc[mi][ni], afr[mi], bfr[ni]);
        }
    }

    #pragma unroll
    for (int mi = 0; mi < 4; mi++) {
        int r0 = m0 + wm + mi * 16 + gid;
        float bv0 = bias[r0];
        float bv1 = bias[r0 + 8];
        #pragma unroll
        for (int ni = 0; ni < 4; ni++) {
            int c0 = n0 + wn + ni * 8 + 2 * tig;
            if (OM == 0) {
                float* Cb = (float*)Cv + (size_t)blockIdx.z * sCb;
                Cb[(size_t)r0 * NN + c0]           = acc[mi][ni][0] + bv0;
                Cb[(size_t)r0 * NN + c0 + 1]       = acc[mi][ni][1] + bv0;
                Cb[(size_t)(r0 + 8) * NN + c0]     = acc[mi][ni][2] + bv1;
                Cb[(size_t)(r0 + 8) * NN + c0 + 1] = acc[mi][ni][3] + bv1;
            } else {
                __half* Cb = (__half*)Cv + (size_t)blockIdx.z * sCb;
                Cb[(size_t)r0 * NN + c0]           = __float2half(acc[mi][ni][0] + bv0);
                Cb[(size_t)r0 * NN + c0 + 1]       = __float2half(acc[mi][ni][1] + bv0);
                Cb[(size_t)(r0 + 8) * NN + c0]     = __float2half(acc[mi][ni][2] + bv1);
                Cb[(size_t)(r0 + 8) * NN + c0 + 1] = __float2half(acc[mi][ni][3] + bv1);
            }
        }
    }
}

// ===========================================================================
// FUSED ATTENTION: one CTA = one (b,h) x 128-pixel n-tile.
//   S[n][t] = scale * sum_d Q[d][n] K[d][t]
//   softmax entirely in registers: each row's 80 cols live in one 4-lane
//   quad (shfl_xor 1,2) -> P (fp16) written into sK region, cols>=77 -> 0
//   O[d][n] = sum_t V[d][t] P[n][t]
// smem: sQ [128d][136]h | sK/sP [128][80]h | sV [128][80]h   = 75776 B
// ===========================================================================
#define FA_SQ 0
#define FA_SK 34816
#define FA_SV 55296
#define FA_SMEM 75776

__global__ __launch_bounds__(256, 2)
void fused_attn(const __half* __restrict__ Q, const __half* __restrict__ KV,
                __half* __restrict__ O, float scale)
{
    extern __shared__ char smem[];
    const uint32_t sb = smem_u32(smem);

    const int tid  = threadIdx.x;
    const int lane = tid & 31;
    const int warp = tid >> 5;
    const int gid = lane >> 2;
    const int tig = lane & 3;
    const int tl  = lane >> 3;
    const int rr  = lane & 7;

    const int n0 = blockIdx.x * 128;
    const int z = blockIdx.y;           // b*8 + h
    const int b = z >> 3, h = z & 7;

    const __half* Qb = Q  + (size_t)b * CC * NN + (size_t)(h * HD) * NN;
    const __half* Kb = KV + (size_t)b * 2 * CC * TP + (size_t)(2 * HD * h) * TP;
    const __half* Vb = Kb + (size_t)HD * TP;

    // ---- load Q tile, K, V ----
    #pragma unroll
    for (int i = 0; i < 8; i++) {       // Q: 128d x 128n
        int c = tid + i * 256;
        int d = c >> 4, o = (c & 15) * 8;
        CP16(sb + FA_SQ + (uint32_t)(d * 136 + o) * 2,
             Qb + (size_t)d * NN + n0 + o, 16);
    }
    #pragma unroll
    for (int i = 0; i < 5; i++) {       // K: 128d x 80t
        int c = tid + i * 256;
        int d = c / 10, o = (c % 10) * 8;
        CP16(sb + FA_SK + (uint32_t)(d * 80 + o) * 2,
             Kb + (size_t)d * TP + o, 16);
    }
    #pragma unroll
    for (int i = 0; i < 5; i++) {       // V: 128d x 80t
        int c = tid + i * 256;
        int d = c / 10, o = (c % 10) * 8;
        CP16(sb + FA_SV + (uint32_t)(d * 80 + o) * 2,
             Vb + (size_t)d * TP + o, 16);
    }
    CP_COMMIT();
    CP_WAIT0();
    __syncthreads();

    // ---- S = Q^T K : warp owns 16 n-rows [warp*16,+16), all 80 t-cols ----
    {
        const int wm = warp * 16;
        float accs[10][4];
        #pragma unroll
        for (int ni = 0; ni < 10; ni++)
            #pragma unroll
            for (int j = 0; j < 4; j++) accs[ni][j] = 0.f;

        #pragma unroll
        for (int kk = 0; kk < 128; kk += 16) {
            uint32_t afr[4];
            uint32_t aaddr = sb + FA_SQ + (uint32_t)((kk + (tl >> 1) * 8 + rr) * 136
                                                     + wm + (tl & 1) * 8) * 2;
            LDSM_X4T(afr[0], afr[1], afr[2], afr[3], aaddr);
            uint32_t bfr[10][2];
            #pragma unroll
            for (int tb = 0; tb < 5; tb++) {
                uint32_t baddr = sb + FA_SK + (uint32_t)((kk + (tl & 1) * 8 + rr) * 80
                                                         + tb * 16 + (tl >> 1) * 8) * 2;
                LDSM_X4T(bfr[2*tb][0], bfr[2*tb][1], bfr[2*tb+1][0], bfr[2*tb+1][1], baddr);
            }
            #pragma unroll
            for (int ni = 0; ni < 10; ni++)
                mma_f16(accs[ni], afr, bfr[ni]);
        }

        // scale in place
        #pragma unroll
        for (int ni = 0; ni < 10; ni++)
            #pragma unroll
            for (int j = 0; j < 4; j++) accs[ni][j] *= scale;

        // row max (cols < 77 only): thread holds cols {ni*8+2tig, +1} for
        // rows wm+gid ([0],[1]) and wm+gid+8 ([2],[3]); quad = 4 lanes of gid.
        float mx0 = -1e30f, mx1 = -1e30f;
        #pragma unroll
        for (int ni = 0; ni < 10; ni++) {
            int c0 = ni * 8 + 2 * tig;
            if (c0 < TT)     { mx0 = fmaxf(mx0, accs[ni][0]); mx1 = fmaxf(mx1, accs[ni][2]); }
            if (c0 + 1 < TT) { mx0 = fmaxf(mx0, accs[ni][1]); mx1 = fmaxf(mx1, accs[ni][3]); }
        }
        mx0 = fmaxf(mx0, __shfl_xor_sync(0xFFFFFFFFu, mx0, 1));
        mx0 = fmaxf(mx0, __shfl_xor_sync(0xFFFFFFFFu, mx0, 2));
        mx1 = fmaxf(mx1, __shfl_xor_sync(0xFFFFFFFFu, mx1, 1));
        mx1 = fmaxf(mx1, __shfl_xor_sync(0xFFFFFFFFu, mx1, 2));

        // exp + row sum
        float s0 = 0.f, s1 = 0.f;
        #pragma unroll
        for (int ni = 0; ni < 10; ni++) {
            int c0 = ni * 8 + 2 * tig;
            float e0 = (c0 < TT)     ? __expf(accs[ni][0] - mx0) : 0.f;
            float e1 = (c0 + 1 < TT) ? __expf(accs[ni][1] - mx0) : 0.f;
            float e2 = (c0 < TT)     ? __expf(accs[ni][2] - mx1) : 0.f;
            float e3 = (c0 + 1 < TT) ? __expf(accs[ni][3] - mx1) : 0.f;
            accs[ni][0] = e0; accs[ni][1] = e1; accs[ni][2] = e2; accs[ni][3] = e3;
            s0 += e0 + e1; s1 += e2 + e3;
        }
        s0 += __shfl_xor_sync(0xFFFFFFFFu, s0, 1);
        s0 += __shfl_xor_sync(0xFFFFFFFFu, s0, 2);
        s1 += __shfl_xor_sync(0xFFFFFFFFu, s1, 1);
        s1 += __shfl_xor_sync(0xFFFFFFFFu, s1, 2);
        float inv0 = 1.f / s0, inv1 = 1.f / s1;

        __syncthreads();   // all warps done reading sK as S operand

        // write P into sK region (half2 stores; invalid cols already 0)
        __half* P = (__half*)(smem + FA_SK);
        #pragma unroll
        for (int ni = 0; ni < 10; ni++) {
            int c0 = ni * 8 + 2 * tig;
            *reinterpret_cast<__half2*>(P + (wm + gid) * 80 + c0) =
                __floats2half2_rn(accs[ni][0] * inv0, accs[ni][1] * inv0);
            *reinterpret_cast<__half2*>(P + (wm + gid + 8) * 80 + c0) =
                __floats2half2_rn(accs[ni][2] * inv1, accs[ni][3] * inv1);
        }
    }
    __syncthreads();

    // ---- O = V P^T : warps 4m(d) x 2n(pixels), warp tile 32x64, K=80 ----
    {
        const int wm2 = (warp & 3) * 32;
        const int wn2 = (warp >> 2) * 64;
        float acco[2][8][4];
        #pragma unroll
        for (int mi = 0; mi < 2; mi++)
            #pragma unroll
            for (int ni = 0; ni < 8; ni++)
                #pragma unroll
                for (int j = 0; j < 4; j++) acco[mi][ni][j] = 0.f;

        #pragma unroll
        for (int kk = 0; kk < 80; kk += 16) {
            uint32_t afr[2][4], bfr[8][2];
            #pragma unroll
            for (int mi = 0; mi < 2; mi++) {
                uint32_t addr = sb + FA_SV + (uint32_t)((wm2 + mi * 16 + (tl & 1) * 8 + rr) * 80
                                                        + kk + (tl >> 1) * 8) * 2;
                LDSM_X4(afr[mi][0], afr[mi][1], afr[mi][2], afr[mi][3], addr);
            }
            #pragma unroll
            for (int np = 0; np < 4; np++) {
                uint32_t addr = sb + FA_SK + (uint32_t)((wn2 + np * 16 + (tl >> 1) * 8 + rr) * 80
                                                        + kk + (tl & 1) * 8) * 2;
                LDSM_X4(bfr[2*np][0], bfr[2*np][1], bfr[2*np+1][0], bfr[2*np+1][1], addr);
            }
            #pragma unroll
            for (int mi = 0; mi < 2; mi++)
                #pragma unroll
                for (int ni = 0; ni < 8; ni++)
                    mma_f16(acco[mi][ni], afr[mi], bfr[ni]);
        }

        __half* Ob = O + (size_t)b * CC * NN + (size_t)(h * HD) * NN;
        #pragma unroll
        for (int mi = 0; mi < 2; mi++) {
            int r0 = wm2 + mi * 16 + gid;
            #pragma unroll
            for (int ni = 0; ni < 8; ni++) {
                int c0 = n0 + wn2 + ni * 8 + 2 * tig;
                Ob[(size_t)r0 * NN + c0]           = __float2half(acco[mi][ni][0]);
                Ob[(size_t)r0 * NN + c0 + 1]       = __float2half(acco[mi][ni][1]);
                Ob[(size_t)(r0 + 8) * NN + c0]     = __float2half(acco[mi][ni][2]);
                Ob[(size_t)(r0 + 8) * NN + c0 + 1] = __float2half(acco[mi][ni][3]);
            }
        }
    }
}

// ===========================================================================
// Small generic GEMM — KV projection only.
// ===========================================================================
#define STAGE_B 20480

template <bool AT, bool BT, int OM>
__global__ __launch_bounds__(256, 2)
void hgemm(const __half* __restrict__ A, const __half* __restrict__ B,
           void* __restrict__ Cv, const float* __restrict__ bias,
           int M, int N, int K,
           long long sA, long long sB, long long ldc,
           long long sAb, long long sAh, long long sBb, long long sBh,
           long long sCb, long long sCh, int nh, float alpha,
           int Ka, int Bbound, int nvalid)
{
    extern __shared__ char smem[];
    const uint32_t sb = smem_u32(smem);

    const int tid  = threadIdx.x;
    const int lane = tid & 31;
    const int warp = tid >> 5;
    const int wm = (warp & 3) * 32;
    const int wn = (warp >> 2) * 64;
    const int gid = lane >> 2;
    const int tig = lane & 3;
    const int tl  = lane >> 3;
    const int rr  = lane & 7;

    const int z = blockIdx.z;
    const int b = z / nh;
    const int h = z - b * nh;
    const __half* Ab = A + (size_t)b * sAb + (size_t)h * sAh;
    const __half* Bb = B + (size_t)b * sBb + (size_t)h * sBh;

    const int m0 = blockIdx.y * 128;
    const int n0 = blockIdx.x * 128;
    const int nkt = (K + 31) >> 5;

    auto load_tile = [&](int kt, int s) {
        const int k0 = kt << 5;
        const uint32_t aB = sb + (uint32_t)s * STAGE_B;
        const uint32_t bB = aB + 10240;
        #pragma unroll
        for (int i = 0; i < 2; i++) {
            int sg = tid + i * 256;
            if (!AT) {
                int m = sg >> 2, sk = sg & 3;
                CP16(aB + (uint32_t)(m * 40 + sk * 8) * 2,
                     Ab + (size_t)(m0 + m) * sA + k0 + sk * 8,
                     (k0 + sk * 8 < Ka) ? 16 : 0);
            } else {
                int k = sg >> 4, sm = sg & 15;
                CP16(aB + (uint32_t)(k * 136 + sm * 8) * 2,
                     Ab + (size_t)(k0 + k) * sA + m0 + sm * 8, 16);
            }
        }
        #pragma unroll
        for (int i = 0; i < 2; i++) {
            int sg = tid + i * 256;
            if (BT) {
                int k = sg >> 4, sn = sg & 15;
                CP16(bB + (uint32_t)(k * 136 + sn * 8) * 2,
                     Bb + (size_t)(k0 + k) * sB + n0 + sn * 8,
                     (n0 + sn * 8 < Bbound) ? 16 : 0);
            } else {
                int n = sg >> 2, sk = sg & 3;
                CP16(bB + (uint32_t)(n * 40 + sk * 8) * 2,
                     Bb + (size_t)(n0 + n) * sB + k0 + sk * 8,
                     (k0 + sk * 8 < Bbound) ? 16 : 0);
            }
        }
        CP_COMMIT();
    };

    float acc[2][8][4];
    #pragma unroll
    for (int mi = 0; mi < 2; mi++)
        #pragma unroll
        for (int ni = 0; ni < 8; ni++)
            #pragma unroll
            for (int j = 0; j < 4; j++) acc[mi][ni][j] = 0.f;

    load_tile(0, 0);
    if (nkt > 1) load_tile(1, 1); else CP_COMMIT();

    for (int kt = 0; kt < nkt; kt++) {
        CP_WAIT1();
        __syncthreads();
        if (kt + 2 < nkt) load_tile(kt + 2, (kt + 2) % 3);
        else CP_COMMIT();

        const uint32_t aB = sb + (uint32_t)((kt % 3) * STAGE_B);
        const uint32_t bB = aB + 10240;

        #pragma unroll
        for (int kk = 0; kk < 32; kk += 16) {
            uint32_t afr[2][4], bfr[8][2];
            #pragma unroll
            for (int mi = 0; mi < 2; mi++) {
                uint32_t addr;
                if (!AT)
                    addr = aB + (uint32_t)((wm + mi * 16 + (tl & 1) * 8 + rr) * 40
                                           + kk + (tl >> 1) * 8) * 2;
                else
                    addr = aB + (uint32_t)((kk + (tl >> 1) * 8 + rr) * 136
                                           + wm + mi * 16 + (tl & 1) * 8) * 2;
                if (!AT) LDSM_X4 (afr[mi][0], afr[mi][1], afr[mi][2], afr[mi][3], addr);
                else     LDSM_X4T(afr[mi][0], afr[mi][1], afr[mi][2], afr[mi][3], addr);
            }
            #pragma unroll
            for (int np = 0; np < 4; np++) {
                int nb = wn + np * 16;
                uint32_t addr;
                if (BT)
                    addr = bB + (uint32_t)((kk + (tl & 1) * 8 + rr) * 136
                                           + nb + (tl >> 1) * 8) * 2;
                else
                    addr = bB + (uint32_t)((nb + (tl >> 1) * 8 + rr) * 40
                                           + kk + (tl & 1) * 8) * 2;
                if (BT) LDSM_X4T(bfr[2*np][0], bfr[2*np][1], bfr[2*np+1][0], bfr[2*np+1][1], addr);
                else    LDSM_X4 (bfr[2*np][0], bfr[2*np][1], bfr[2*np+1][0], bfr[2*np+1][1], addr);
            }
            #pragma unroll
            for (int mi = 0; mi < 2; mi++)
                #pragma unroll
                for (int ni = 0; ni < 8; ni++)
                    mma_f16(acc[mi][ni], afr[mi], bfr[ni]);
        }
    }

    if (OM == 1) {
        __half* Cb = (__half*)Cv + (size_t)b * sCb + (size_t)h * sCh;
        #pragma unroll
        for (int mi = 0; mi < 2; mi++) {
            int r0 = m0 + wm + mi * 16 + gid;
            float bv0 = bias ? bias[r0]     : 0.f;
            float bv1 = bias ? bias[r0 + 8] : 0.f;
            #pragma unroll
            for (int ni = 0; ni < 8; ni++) {
                int c0 = n0 + wn + ni * 8 + 2 * tig;
                if (c0 < N) {
                    #pragma unroll
                    for (int j = 0; j < 2; j++) {
                        int c = c0 + j;
                        bool v = (c < nvalid);
                        Cb[(size_t)r0 * ldc + c] =
                            __float2half(v ? alpha * acc[mi][ni][j] + bv0 : 0.f);
                        Cb[(size_t)(r0 + 8) * ldc + c] =
                            __float2half(v ? alpha * acc[mi][ni][2 + j] + bv1 : 0.f);
                    }
                }
            }
        }
    }
}

// ---------------------------------------------------------------- converters
#define N4_VX  (NB * CC * NN / 4)
#define N4_WQ  (CC * CC / 4)
#define N4_WKV (2 * CC * CC / 4)

__global__ void f2h_all(const float* __restrict__ Vx, const float* __restrict__ Wq,
                        const float* __restrict__ Wkv, const float* __restrict__ Wp,
                        __half* __restrict__ dVx, __half* __restrict__ dWq,
                        __half* __restrict__ dWkv, __half* __restrict__ dWp)
{
    int i = blockIdx.x * 256 + threadIdx.x;
    const float* s; __half* d; int j;
    if (i < N4_VX)                       { s = Vx;  d = dVx;  j = i; }
    else if (i < N4_VX + N4_WQ)          { s = Wq;  d = dWq;  j = i - N4_VX; }
    else if (i < N4_VX + N4_WQ + N4_WKV) { s = Wkv; d = dWkv; j = i - N4_VX - N4_WQ; }
    else                                 { s = Wp;  d = dWp;  j = i - N4_VX - N4_WQ - N4_WKV; }
    float4 v = reinterpret_cast<const float4*>(s)[j];
    __half2* d2 = reinterpret_cast<__half2*>(d);
    d2[2 * j]     = __floats2half2_rn(v.x, v.y);
    d2[2 * j + 1] = __floats2half2_rn(v.z, v.w);
}
__global__ void f2h_pad77(const float* __restrict__ s, __half* __restrict__ d, int rows)
{
    int r = blockIdx.x, c = threadIdx.x;
    if (c < TP)
        d[(size_t)r * TP + c] = __float2half((c < TT) ? s[(size_t)r * TT + c] : 0.f);
}

// ---------------------------------------------------------------- launch
extern "C" void kernel_launch(void* const* d_in, const int* in_sizes, int n_in,
                              void* d_out, int out_size)
{
    const float* Vx  = (const float*)d_in[0];
    const float* Tx  = (const float*)d_in[1];
    const float* Wq  = (const float*)d_in[2];
    const float* bq  = (const float*)d_in[3];
    const float* Wkv = (const float*)d_in[4];
    const float* bkv = (const float*)d_in[5];
    const float* Wp  = (const float*)d_in[6];
    const float* bp  = (const float*)d_in[7];
    float* Y = (float*)d_out;

    __half *hVx, *hTx, *hWq, *hWkv, *hWp, *hQ, *hKV, *hO;
    cudaGetSymbolAddress((void**)&hVx, h_Vx);
    cudaGetSymbolAddress((void**)&hTx, h_Tx);
    cudaGetSymbolAddress((void**)&hWq, h_Wq);
    cudaGetSymbolAddress((void**)&hWkv, h_Wkv);
    cudaGetSymbolAddress((void**)&hWp, h_Wp);
    cudaGetSymbolAddress((void**)&hQ,  h_Q);
    cudaGetSymbolAddress((void**)&hKV, h_KV);
    cudaGetSymbolAddress((void**)&hO,  h_O);

    constexpr int SMEM_SMALL = STAGE_B * 3;   // 61440
    cudaFuncSetAttribute(hgemm<false, true, 1>, cudaFuncAttributeMaxDynamicSharedMemorySize, SMEM_SMALL);
    cudaFuncSetAttribute(hgemm_big<1>, cudaFuncAttributeMaxDynamicSharedMemorySize, BIG_SMEM);
    cudaFuncSetAttribute(hgemm_big<0>, cudaFuncAttributeMaxDynamicSharedMemorySize, BIG_SMEM);
    cudaFuncSetAttribute(fused_attn, cudaFuncAttributeMaxDynamicSharedMemorySize, FA_SMEM);

    const float scale = 0.08838834764831843f;  // 1/sqrt(128)

    // 0) fp32 -> fp16
    f2h_all<<<(N4_VX + N4_WQ + N4_WKV + N4_WQ) / 256, 256>>>(
        Vx, Wq, Wkv, Wp, hVx, hWq, hWkv, hWp);
    f2h_pad77<<<NB * CC, 128>>>(Tx, hTx, NB * CC);

    // 1) KV = Wkv @ Tx + bkv : M=2048, N=80(valid 77), K=1024, per-b
    hgemm<false, true, 1><<<dim3(1, 16, NB), 256, SMEM_SMALL>>>(
        hWkv, hTx, hKV, bkv, 2048, TP, CC,
        CC, TP, TP,
        0, 0, (long long)CC * TP, 0,
        (long long)2 * CC * TP, 0, 1, 1.0f, CC, TP, TT);

    // 2) Q = Wq @ Vx + bq : M=1024, N=1024, K=1024, per-b  [BIG BK=64]
    hgemm_big<1><<<dim3(8, 4, NB), 512, BIG_SMEM>>>(
        hWq, hVx, hQ, bq, (long long)CC * NN, (long long)CC * NN);

    // 3) fused attention: S -> register softmax -> O, per (b,h) x n-tile
    fused_attn<<<dim3(8, NB * NH), 256, FA_SMEM>>>(hQ, hKV, hO, scale);

    // 4) Y = Wp @ O + bp : M=1024, N=1024, K=1024, per-b, fp32 out  [BIG BK=64]
    hgemm_big<0><<<dim3(8, 4, NB), 512, BIG_SMEM>>>(
        hWp, hO, Y, bp, (long long)CC * NN, (long long)CC * NN);
}